// round 5
// baseline (speedup 1.0000x reference)
#include <cuda_runtime.h>

// out = x[0]; out[c, ix, iy] += img[c, proj_y, proj_x]
// Channel-split position-major scratch: each scatter pass's working set
// (imgT_h 32MB + accT_h 32MB) is L2-resident (126MB L2); 32 B per record per
// side = exactly one L2 sector.
// R5: vectorized transposes (float4 both sides), 2-record scatter ILP,
// vectorized pack/finish.

#define HW (1024 * 1024)
#define LMAX 4000000

__device__ float g_imgT0[(size_t)HW * 8];
__device__ float g_imgT1[(size_t)HW * 8];
__device__ float g_accT0[(size_t)HW * 8];
__device__ float g_accT1[(size_t)HW * 8];
__device__ int2  g_pk[LMAX];

__device__ __forceinline__ void red_add_v4(float* ptr, float4 v) {
    asm volatile("red.global.add.v4.f32 [%0], {%1, %2, %3, %4};"
                 :: "l"(ptr), "f"(v.x), "f"(v.y), "f"(v.z), "f"(v.w)
                 : "memory");
}

// Transpose one 8-channel half of a channel-major source into a
// position-major dest. Each thread: 4 consecutive positions.
// Loads: 8x float4 (fully coalesced). Stores: 128 B contiguous per thread.
__device__ __forceinline__ void transpose_half(const float* __restrict__ src,
                                               float* __restrict__ dstT,
                                               int p4) {
    float4 r[8];
#pragma unroll
    for (int c = 0; c < 8; c++) {
        r[c] = __ldg((const float4*)(src + (size_t)c * HW + p4));
    }
    float4* d = (float4*)(dstT + (size_t)p4 * 8);
    // position p4+j gets channels 0..7: two float4 stores each
    d[0] = make_float4(r[0].x, r[1].x, r[2].x, r[3].x);
    d[1] = make_float4(r[4].x, r[5].x, r[6].x, r[7].x);
    d[2] = make_float4(r[0].y, r[1].y, r[2].y, r[3].y);
    d[3] = make_float4(r[4].y, r[5].y, r[6].y, r[7].y);
    d[4] = make_float4(r[0].z, r[1].z, r[2].z, r[3].z);
    d[5] = make_float4(r[4].z, r[5].z, r[6].z, r[7].z);
    d[6] = make_float4(r[0].w, r[1].w, r[2].w, r[3].w);
    d[7] = make_float4(r[4].w, r[5].w, r[6].w, r[7].w);
}

__global__ void __launch_bounds__(256) prep_kernel(const float* __restrict__ x,
                                                   const float* __restrict__ img) {
    int p4 = (blockIdx.x * blockDim.x + threadIdx.x) * 4;
    if (p4 >= HW) return;
    transpose_half(x,            g_accT0, p4);
    transpose_half(x + 8 * (size_t)HW,  g_accT1, p4);
    transpose_half(img,          g_imgT0, p4);
    transpose_half(img + 8 * (size_t)HW, g_imgT1, p4);
}

// Pack (src, dst) per record, 4 records per thread.
__global__ void __launch_bounds__(256) pack_kernel(const int* __restrict__ index_x,
                                                   const int* __restrict__ index_y,
                                                   const int* __restrict__ proj_x,
                                                   const int* __restrict__ proj_y,
                                                   int L) {
    int l4 = (blockIdx.x * blockDim.x + threadIdx.x) * 4;
    if (l4 + 3 < L) {
        int4 ix = __ldg((const int4*)(index_x + l4));
        int4 iy = __ldg((const int4*)(index_y + l4));
        int4 px = __ldg((const int4*)(proj_x + l4));
        int4 py = __ldg((const int4*)(proj_y + l4));
        int2* o = g_pk + l4;
        o[0] = make_int2(py.x * 1024 + px.x, ix.x * 1024 + iy.x);
        o[1] = make_int2(py.y * 1024 + px.y, ix.y * 1024 + iy.y);
        o[2] = make_int2(py.z * 1024 + px.z, ix.z * 1024 + iy.z);
        o[3] = make_int2(py.w * 1024 + px.w, ix.w * 1024 + iy.w);
    } else {
        for (int l = l4; l < L; l++) {
            g_pk[l] = make_int2(__ldg(proj_y + l) * 1024 + __ldg(proj_x + l),
                                __ldg(index_x + l) * 1024 + __ldg(index_y + l));
        }
    }
}

// One channel-half scatter pass. 2 records per thread for MLP.
template <int HALF>
__global__ void __launch_bounds__(256) scatter_half(int L) {
    const float* __restrict__ imgTh = (HALF == 0) ? g_imgT0 : g_imgT1;
    float* __restrict__ accTh       = (HALF == 0) ? g_accT0 : g_accT1;

    int l2 = (blockIdx.x * blockDim.x + threadIdx.x) * 2;
    if (l2 + 1 < L) {
        int4 k = __ldg((const int4*)(g_pk + l2));  // 2 records: (src0,dst0,src1,dst1)
        const float4* s0 = (const float4*)(imgTh + (size_t)k.x * 8);
        const float4* s1 = (const float4*)(imgTh + (size_t)k.z * 8);
        float4 a0 = __ldg(s0 + 0);
        float4 a1 = __ldg(s0 + 1);
        float4 b0 = __ldg(s1 + 0);
        float4 b1 = __ldg(s1 + 1);
        float* d0 = accTh + (size_t)k.y * 8;
        float* d1 = accTh + (size_t)k.w * 8;
        red_add_v4(d0 + 0, a0);
        red_add_v4(d0 + 4, a1);
        red_add_v4(d1 + 0, b0);
        red_add_v4(d1 + 4, b1);
    } else if (l2 < L) {
        int2 k = __ldg(g_pk + l2);
        const float4* s = (const float4*)(imgTh + (size_t)k.x * 8);
        float4 v0 = __ldg(s + 0);
        float4 v1 = __ldg(s + 1);
        float* d = accTh + (size_t)k.y * 8;
        red_add_v4(d + 0, v0);
        red_add_v4(d + 4, v1);
    }
}

// accT halves (position-major) -> out (channel-major). 4 positions/thread:
// reads 2x128 B contiguous, writes float4 per plane (coalesced).
__global__ void __launch_bounds__(256) finish_kernel(float* __restrict__ out) {
    int p4 = (blockIdx.x * blockDim.x + threadIdx.x) * 4;
    if (p4 >= HW) return;

    const float4* a0 = (const float4*)(g_accT0 + (size_t)p4 * 8);
    const float4* a1 = (const float4*)(g_accT1 + (size_t)p4 * 8);
    float4 v0[8], v1[8];
#pragma unroll
    for (int i = 0; i < 8; i++) { v0[i] = a0[i]; v1[i] = a1[i]; }
    const float* f0 = (const float*)v0;  // f0[j*8 + c] = acc[p4+j][c],   c<8
    const float* f1 = (const float*)v1;  // f1[j*8 + c] = acc[p4+j][c+8]
#pragma unroll
    for (int c = 0; c < 8; c++) {
        *(float4*)(out + (size_t)c * HW + p4) =
            make_float4(f0[0*8+c], f0[1*8+c], f0[2*8+c], f0[3*8+c]);
        *(float4*)(out + (size_t)(c + 8) * HW + p4) =
            make_float4(f1[0*8+c], f1[1*8+c], f1[2*8+c], f1[3*8+c]);
    }
}

extern "C" void kernel_launch(void* const* d_in, const int* in_sizes, int n_in,
                              void* d_out, int out_size) {
    const float* x       = (const float*)d_in[0];
    const float* img     = (const float*)d_in[1];
    const int*   index_x = (const int*)d_in[2];
    const int*   index_y = (const int*)d_in[3];
    const int*   proj_x  = (const int*)d_in[4];
    const int*   proj_y  = (const int*)d_in[5];
    float*       out     = (float*)d_out;

    const int L = in_sizes[2];
    const int T = 256;

    prep_kernel<<<HW / 4 / T, T>>>(x, img);
    pack_kernel<<<(L / 4 + T - 1) / T, T>>>(index_x, index_y, proj_x, proj_y, L);
    int scatter_blocks = ((L + 1) / 2 + T - 1) / T;
    scatter_half<0><<<scatter_blocks, T>>>(L);
    scatter_half<1><<<scatter_blocks, T>>>(L);
    finish_kernel<<<HW / 4 / T, T>>>(out);
}

// round 6
// speedup vs baseline: 1.1804x; 1.1804x over previous
#include <cuda_runtime.h>

// out = x[0]; out[c, ix, iy] += img[c, proj_y, proj_x]
// Channel-split position-major scratch: each scatter pass's working set
// (imgT_h 32MB + accT_h 32MB) is L2-resident (126MB L2); 32 B per record per
// side = exactly one L2 sector.
// R6: R4 skeleton; pack kernel removed (scatters read raw indices, 4 rec/thr);
// prep does 2 positions/thread with float2 loads, phased to cap registers.

#define HW (1024 * 1024)

__device__ float g_imgT0[(size_t)HW * 8];
__device__ float g_imgT1[(size_t)HW * 8];
__device__ float g_accT0[(size_t)HW * 8];
__device__ float g_accT1[(size_t)HW * 8];

__device__ __forceinline__ void red_add_v4(float* ptr, float4 v) {
    asm volatile("red.global.add.v4.f32 [%0], {%1, %2, %3, %4};"
                 :: "l"(ptr), "f"(v.x), "f"(v.y), "f"(v.z), "f"(v.w)
                 : "memory");
}

// Transpose 16 channels of one channel-major tensor into two position-major
// half tensors, 2 positions per thread. Loads float2 per channel (coalesced),
// stores 2x float4 per (position, half) — contiguous per thread.
__device__ __forceinline__ void prep_one(const float* __restrict__ src,
                                         float* __restrict__ dstT0,
                                         float* __restrict__ dstT1,
                                         int p2) {
    float2 r[16];
#pragma unroll
    for (int c = 0; c < 16; c++) {
        r[c] = __ldg((const float2*)(src + (size_t)c * HW + p2));
    }
    float4* d0 = (float4*)(dstT0 + (size_t)p2 * 8);
    float4* d1 = (float4*)(dstT1 + (size_t)p2 * 8);
    d0[0] = make_float4(r[0].x,  r[1].x,  r[2].x,  r[3].x);
    d0[1] = make_float4(r[4].x,  r[5].x,  r[6].x,  r[7].x);
    d0[2] = make_float4(r[0].y,  r[1].y,  r[2].y,  r[3].y);
    d0[3] = make_float4(r[4].y,  r[5].y,  r[6].y,  r[7].y);
    d1[0] = make_float4(r[8].x,  r[9].x,  r[10].x, r[11].x);
    d1[1] = make_float4(r[12].x, r[13].x, r[14].x, r[15].x);
    d1[2] = make_float4(r[8].y,  r[9].y,  r[10].y, r[11].y);
    d1[3] = make_float4(r[12].y, r[13].y, r[14].y, r[15].y);
}

__global__ void __launch_bounds__(256) prep_kernel(const float* __restrict__ x,
                                                   const float* __restrict__ img) {
    int p2 = (blockIdx.x * blockDim.x + threadIdx.x) * 2;
    if (p2 >= HW) return;
    prep_one(x,   g_accT0, g_accT1, p2);
    prep_one(img, g_imgT0, g_imgT1, p2);
}

// One channel-half scatter pass, 4 records/thread, raw index arrays.
template <int HALF>
__global__ void __launch_bounds__(256) scatter_half(const int* __restrict__ index_x,
                                                    const int* __restrict__ index_y,
                                                    const int* __restrict__ proj_x,
                                                    const int* __restrict__ proj_y,
                                                    int L) {
    const float* __restrict__ imgTh = (HALF == 0) ? g_imgT0 : g_imgT1;
    float* __restrict__ accTh       = (HALF == 0) ? g_accT0 : g_accT1;

    int l4 = (blockIdx.x * blockDim.x + threadIdx.x) * 4;
    if (l4 + 3 < L) {
        int4 ix = __ldg((const int4*)(index_x + l4));
        int4 iy = __ldg((const int4*)(index_y + l4));
        int4 px = __ldg((const int4*)(proj_x + l4));
        int4 py = __ldg((const int4*)(proj_y + l4));

        int s0 = py.x * 1024 + px.x, d0 = ix.x * 1024 + iy.x;
        int s1 = py.y * 1024 + px.y, d1 = ix.y * 1024 + iy.y;
        int s2 = py.z * 1024 + px.z, d2 = ix.z * 1024 + iy.z;
        int s3 = py.w * 1024 + px.w, d3 = ix.w * 1024 + iy.w;

        const float4* g0 = (const float4*)(imgTh + (size_t)s0 * 8);
        const float4* g1 = (const float4*)(imgTh + (size_t)s1 * 8);
        const float4* g2 = (const float4*)(imgTh + (size_t)s2 * 8);
        const float4* g3 = (const float4*)(imgTh + (size_t)s3 * 8);
        float4 a0 = __ldg(g0 + 0), a1 = __ldg(g0 + 1);
        float4 b0 = __ldg(g1 + 0), b1 = __ldg(g1 + 1);
        float4 c0 = __ldg(g2 + 0), c1 = __ldg(g2 + 1);
        float4 e0 = __ldg(g3 + 0), e1 = __ldg(g3 + 1);

        float* w0 = accTh + (size_t)d0 * 8;
        float* w1 = accTh + (size_t)d1 * 8;
        float* w2 = accTh + (size_t)d2 * 8;
        float* w3 = accTh + (size_t)d3 * 8;
        red_add_v4(w0 + 0, a0); red_add_v4(w0 + 4, a1);
        red_add_v4(w1 + 0, b0); red_add_v4(w1 + 4, b1);
        red_add_v4(w2 + 0, c0); red_add_v4(w2 + 4, c1);
        red_add_v4(w3 + 0, e0); red_add_v4(w3 + 4, e1);
    } else {
        for (int l = l4; l < L; l++) {
            int src = __ldg(proj_y + l) * 1024 + __ldg(proj_x + l);
            int dst = __ldg(index_x + l) * 1024 + __ldg(index_y + l);
            const float4* s = (const float4*)(imgTh + (size_t)src * 8);
            float4 v0 = __ldg(s + 0);
            float4 v1 = __ldg(s + 1);
            float* d = accTh + (size_t)dst * 8;
            red_add_v4(d + 0, v0);
            red_add_v4(d + 4, v1);
        }
    }
}

// accT halves (position-major) -> out (channel-major). R4 version (known good).
__global__ void __launch_bounds__(256) finish_kernel(float* __restrict__ out) {
    int p = blockIdx.x * blockDim.x + threadIdx.x;
    if (p >= HW) return;

    const float4* a0 = (const float4*)(g_accT0 + (size_t)p * 8);
    const float4* a1 = (const float4*)(g_accT1 + (size_t)p * 8);
    float4 v[4];
    v[0] = a0[0]; v[1] = a0[1]; v[2] = a1[0]; v[3] = a1[1];
    const float* f = (const float*)v;
#pragma unroll
    for (int c = 0; c < 16; c++) {
        out[(size_t)c * HW + p] = f[c];
    }
}

extern "C" void kernel_launch(void* const* d_in, const int* in_sizes, int n_in,
                              void* d_out, int out_size) {
    const float* x       = (const float*)d_in[0];
    const float* img     = (const float*)d_in[1];
    const int*   index_x = (const int*)d_in[2];
    const int*   index_y = (const int*)d_in[3];
    const int*   proj_x  = (const int*)d_in[4];
    const int*   proj_y  = (const int*)d_in[5];
    float*       out     = (float*)d_out;

    const int L = in_sizes[2];
    const int T = 256;

    prep_kernel<<<HW / 2 / T, T>>>(x, img);
    int sb = (L / 4 + T - 1) / T + 1;
    scatter_half<0><<<sb, T>>>(index_x, index_y, proj_x, proj_y, L);
    scatter_half<1><<<sb, T>>>(index_x, index_y, proj_x, proj_y, L);
    finish_kernel<<<(HW + T - 1) / T, T>>>(out);
}

// round 7
// speedup vs baseline: 1.2443x; 1.0541x over previous
#include <cuda_runtime.h>

// out = x[0]; out[c, ix, iy] += img[c, proj_y, proj_x]
// Channel-split position-major scratch (each half: imgT_h 32MB + accT_h 32MB,
// L2-resident). R7: overlap independent per-half phases by fusing roles into
// shared grids on one stream:
//   A: prep half0
//   B: scatter half0 || prep half1
//   C: scatter half1 || finish half0
//   D: finish half1

#define HW (1024 * 1024)

__device__ float g_imgT0[(size_t)HW * 8];
__device__ float g_imgT1[(size_t)HW * 8];
__device__ float g_accT0[(size_t)HW * 8];
__device__ float g_accT1[(size_t)HW * 8];

__device__ __forceinline__ void red_add_v4(float* ptr, float4 v) {
    asm volatile("red.global.add.v4.f32 [%0], {%1, %2, %3, %4};"
                 :: "l"(ptr), "f"(v.x), "f"(v.y), "f"(v.z), "f"(v.w)
                 : "memory");
}

// ---- role bodies (block-level) ------------------------------------------

// Transpose 8 channels [8h, 8h+8) of x and img into accT_h / imgT_h.
// 2 positions per thread, float2 loads, float4 stores.
template <int HALF>
__device__ __forceinline__ void prep_block(const float* __restrict__ x,
                                           const float* __restrict__ img,
                                           int pb, int tid) {
    float* __restrict__ accTh = (HALF == 0) ? g_accT0 : g_accT1;
    float* __restrict__ imgTh = (HALF == 0) ? g_imgT0 : g_imgT1;
    const size_t choff = (size_t)(HALF * 8) * HW;

    int p2 = (pb * 256 + tid) * 2;
    if (p2 >= HW) return;

    float2 r[8];
#pragma unroll
    for (int c = 0; c < 8; c++)
        r[c] = __ldg((const float2*)(x + choff + (size_t)c * HW + p2));
    float4* d = (float4*)(accTh + (size_t)p2 * 8);
    d[0] = make_float4(r[0].x, r[1].x, r[2].x, r[3].x);
    d[1] = make_float4(r[4].x, r[5].x, r[6].x, r[7].x);
    d[2] = make_float4(r[0].y, r[1].y, r[2].y, r[3].y);
    d[3] = make_float4(r[4].y, r[5].y, r[6].y, r[7].y);

#pragma unroll
    for (int c = 0; c < 8; c++)
        r[c] = __ldg((const float2*)(img + choff + (size_t)c * HW + p2));
    float4* e = (float4*)(imgTh + (size_t)p2 * 8);
    e[0] = make_float4(r[0].x, r[1].x, r[2].x, r[3].x);
    e[1] = make_float4(r[4].x, r[5].x, r[6].x, r[7].x);
    e[2] = make_float4(r[0].y, r[1].y, r[2].y, r[3].y);
    e[3] = make_float4(r[4].y, r[5].y, r[6].y, r[7].y);
}

// Scatter-add 4 records per thread within one half (R6's proven body).
template <int HALF>
__device__ __forceinline__ void scatter_block(const int* __restrict__ index_x,
                                              const int* __restrict__ index_y,
                                              const int* __restrict__ proj_x,
                                              const int* __restrict__ proj_y,
                                              int L, int sb, int tid) {
    const float* __restrict__ imgTh = (HALF == 0) ? g_imgT0 : g_imgT1;
    float* __restrict__ accTh       = (HALF == 0) ? g_accT0 : g_accT1;

    int l4 = (sb * 256 + tid) * 4;
    if (l4 + 3 < L) {
        int4 ix = __ldg((const int4*)(index_x + l4));
        int4 iy = __ldg((const int4*)(index_y + l4));
        int4 px = __ldg((const int4*)(proj_x + l4));
        int4 py = __ldg((const int4*)(proj_y + l4));

        int s0 = py.x * 1024 + px.x, d0 = ix.x * 1024 + iy.x;
        int s1 = py.y * 1024 + px.y, d1 = ix.y * 1024 + iy.y;
        int s2 = py.z * 1024 + px.z, d2 = ix.z * 1024 + iy.z;
        int s3 = py.w * 1024 + px.w, d3 = ix.w * 1024 + iy.w;

        const float4* g0 = (const float4*)(imgTh + (size_t)s0 * 8);
        const float4* g1 = (const float4*)(imgTh + (size_t)s1 * 8);
        const float4* g2 = (const float4*)(imgTh + (size_t)s2 * 8);
        const float4* g3 = (const float4*)(imgTh + (size_t)s3 * 8);
        float4 a0 = __ldg(g0 + 0), a1 = __ldg(g0 + 1);
        float4 b0 = __ldg(g1 + 0), b1 = __ldg(g1 + 1);
        float4 c0 = __ldg(g2 + 0), c1 = __ldg(g2 + 1);
        float4 e0 = __ldg(g3 + 0), e1 = __ldg(g3 + 1);

        float* w0 = accTh + (size_t)d0 * 8;
        float* w1 = accTh + (size_t)d1 * 8;
        float* w2 = accTh + (size_t)d2 * 8;
        float* w3 = accTh + (size_t)d3 * 8;
        red_add_v4(w0 + 0, a0); red_add_v4(w0 + 4, a1);
        red_add_v4(w1 + 0, b0); red_add_v4(w1 + 4, b1);
        red_add_v4(w2 + 0, c0); red_add_v4(w2 + 4, c1);
        red_add_v4(w3 + 0, e0); red_add_v4(w3 + 4, e1);
    } else {
        for (int l = l4; l < L; l++) {
            int src = __ldg(proj_y + l) * 1024 + __ldg(proj_x + l);
            int dst = __ldg(index_x + l) * 1024 + __ldg(index_y + l);
            const float4* s = (const float4*)(imgTh + (size_t)src * 8);
            float4 v0 = __ldg(s + 0);
            float4 v1 = __ldg(s + 1);
            float* d = accTh + (size_t)dst * 8;
            red_add_v4(d + 0, v0);
            red_add_v4(d + 4, v1);
        }
    }
}

// Write out channels [8h, 8h+8) from accT_h. 2 positions/thread.
template <int HALF>
__device__ __forceinline__ void finish_block(float* __restrict__ out,
                                             int fb, int tid) {
    const float* __restrict__ accTh = (HALF == 0) ? g_accT0 : g_accT1;
    const size_t choff = (size_t)(HALF * 8) * HW;

    int p2 = (fb * 256 + tid) * 2;
    if (p2 >= HW) return;

    float4 v[4];
    const float4* a = (const float4*)(accTh + (size_t)p2 * 8);
#pragma unroll
    for (int i = 0; i < 4; i++) v[i] = a[i];
    const float* f = (const float*)v;  // f[j*8 + c] = acc[p2+j][c]
#pragma unroll
    for (int c = 0; c < 8; c++) {
        *(float2*)(out + choff + (size_t)c * HW + p2) =
            make_float2(f[c], f[8 + c]);
    }
}

// ---- kernels --------------------------------------------------------------

#define NPREP  (HW / 2 / 256)   // 2048 blocks per half-prep / half-finish

__global__ void __launch_bounds__(256) kA_prep0(const float* __restrict__ x,
                                                const float* __restrict__ img) {
    prep_block<0>(x, img, blockIdx.x, threadIdx.x);
}

// B: scatter half0 (2 of every 3 blocks) || prep half1 (1 of every 3)
__global__ void __launch_bounds__(256) kB(const float* __restrict__ x,
                                          const float* __restrict__ img,
                                          const int* __restrict__ index_x,
                                          const int* __restrict__ index_y,
                                          const int* __restrict__ proj_x,
                                          const int* __restrict__ proj_y,
                                          int L, int NS) {
    int g = blockIdx.x / 3, r = blockIdx.x % 3;
    if (r < 2) {
        int sb = g * 2 + r;
        if (sb < NS) scatter_block<0>(index_x, index_y, proj_x, proj_y, L, sb, threadIdx.x);
    } else {
        if (g < NPREP) prep_block<1>(x, img, g, threadIdx.x);
    }
}

// C: scatter half1 || finish half0
__global__ void __launch_bounds__(256) kC(float* __restrict__ out,
                                          const int* __restrict__ index_x,
                                          const int* __restrict__ index_y,
                                          const int* __restrict__ proj_x,
                                          const int* __restrict__ proj_y,
                                          int L, int NS) {
    int g = blockIdx.x / 3, r = blockIdx.x % 3;
    if (r < 2) {
        int sb = g * 2 + r;
        if (sb < NS) scatter_block<1>(index_x, index_y, proj_x, proj_y, L, sb, threadIdx.x);
    } else {
        if (g < NPREP) finish_block<0>(out, g, threadIdx.x);
    }
}

__global__ void __launch_bounds__(256) kD_finish1(float* __restrict__ out) {
    finish_block<1>(out, blockIdx.x, threadIdx.x);
}

extern "C" void kernel_launch(void* const* d_in, const int* in_sizes, int n_in,
                              void* d_out, int out_size) {
    const float* x       = (const float*)d_in[0];
    const float* img     = (const float*)d_in[1];
    const int*   index_x = (const int*)d_in[2];
    const int*   index_y = (const int*)d_in[3];
    const int*   proj_x  = (const int*)d_in[4];
    const int*   proj_y  = (const int*)d_in[5];
    float*       out     = (float*)d_out;

    const int L = in_sizes[2];

    int NS = (L / 4 + 255) / 256 + 1;                 // scatter blocks (tail-safe)
    int groups = ((NS + 1) / 2 > NPREP) ? (NS + 1) / 2 : NPREP;
    int NB = 3 * groups;

    kA_prep0<<<NPREP, 256>>>(x, img);
    kB<<<NB, 256>>>(x, img, index_x, index_y, proj_x, proj_y, L, NS);
    kC<<<NB, 256>>>(out, index_x, index_y, proj_x, proj_y, L, NS);
    kD_finish1<<<NPREP, 256>>>(out);
}